// round 16
// baseline (speedup 1.0000x reference)
#include <cuda_runtime.h>
#include <cuda_bf16.h>
#include <cuda_fp16.h>
#include <math.h>
#include <stdint.h>

// Problem constants
#define SEQ    2048
#define DMODEL 4096
#define NHEAD  32
#define NKVH   8
#define HDIM   128
#define KVD    (NKVH * HDIM)     // 1024
#define ATT_SCALE 0.08838834764831845f

// ---------------------------------------------------------------------------
// Helpers
// ---------------------------------------------------------------------------
__device__ __forceinline__ uint32_t smem_u32(const void* p) {
    uint32_t a;
    asm("{ .reg .u64 t; cvta.to.shared.u64 t, %1; cvt.u32.u64 %0, t; }" : "=r"(a) : "l"(p));
    return a;
}
__device__ __forceinline__ void ldsm_x4(uint32_t* r, uint32_t addr) {
    asm volatile("ldmatrix.sync.aligned.m8n8.x4.shared.b16 {%0,%1,%2,%3}, [%4];"
                 : "=r"(r[0]), "=r"(r[1]), "=r"(r[2]), "=r"(r[3]) : "r"(addr));
}
__device__ __forceinline__ void ldsm_x4_t(uint32_t* r, uint32_t addr) {
    asm volatile("ldmatrix.sync.aligned.m8n8.x4.trans.shared.b16 {%0,%1,%2,%3}, [%4];"
                 : "=r"(r[0]), "=r"(r[1]), "=r"(r[2]), "=r"(r[3]) : "r"(addr));
}
// f16 inputs, f32 accumulator
__device__ __forceinline__ void mma16816h(float* c, const uint32_t* a, const uint32_t* b) {
    asm volatile("mma.sync.aligned.m16n8k16.row.col.f32.f16.f16.f32 "
                 "{%0,%1,%2,%3}, {%4,%5,%6,%7}, {%8,%9}, {%0,%1,%2,%3};"
                 : "+f"(c[0]), "+f"(c[1]), "+f"(c[2]), "+f"(c[3])
                 : "r"(a[0]), "r"(a[1]), "r"(a[2]), "r"(a[3]), "r"(b[0]), "r"(b[1]));
}
// f16 inputs, f16 accumulator (2 regs = 4 halves); rate experiment
__device__ __forceinline__ void mma16816hh(uint32_t* c, const uint32_t* a, const uint32_t* b) {
    asm volatile("mma.sync.aligned.m16n8k16.row.col.f16.f16.f16.f16 "
                 "{%0,%1}, {%2,%3,%4,%5}, {%6,%7}, {%0,%1};"
                 : "+r"(c[0]), "+r"(c[1])
                 : "r"(a[0]), "r"(a[1]), "r"(a[2]), "r"(a[3]), "r"(b[0]), "r"(b[1]));
}
__device__ __forceinline__ void cp16(uint32_t dst, const void* src) {
    asm volatile("cp.async.cg.shared.global [%0], [%1], 16;" :: "r"(dst), "l"(src));
}
__device__ __forceinline__ uint32_t packh2(__half a, __half b) {
    __half2 h = __halves2half2(a, b);
    return *(uint32_t*)&h;
}

// ---------------------------------------------------------------------------
// Scratch (device globals; no allocation allowed)
// ---------------------------------------------------------------------------
__device__ __half g_qh[SEQ * DMODEL], g_ql[SEQ * DMODEL];  // rope'd+scaled Q split
__device__ __half g_kh[SEQ * KVD], g_kl[SEQ * KVD];        // rope'd K split
__device__ __half g_vh[SEQ * KVD];                         // V fp16

__device__ __half a_hi[SEQ * DMODEL], a_lo[SEQ * DMODEL];      // x split
__device__ __half att_hi[SEQ * DMODEL], att_lo[SEQ * DMODEL];  // attention out split
__device__ __half wqT_h[DMODEL * DMODEL], wqT_l[DMODEL * DMODEL];
__device__ __half wkT_h[KVD * DMODEL],  wkT_l[KVD * DMODEL];
__device__ __half wvT_h[KVD * DMODEL],  wvT_l[KVD * DMODEL];
__device__ __half woT_h[DMODEL * DMODEL], woT_l[DMODEL * DMODEL];

// ---------------------------------------------------------------------------
// Elementwise fp32 -> fp16 hi/lo split of x
// ---------------------------------------------------------------------------
__global__ void convert_x(const float* __restrict__ x)
{
    int i = blockIdx.x * blockDim.x + threadIdx.x;   // < 2M
    float4 v = *(const float4*)&x[(size_t)i * 4];
    float f[4] = {v.x, v.y, v.z, v.w};
#pragma unroll
    for (int j = 0; j < 4; j++) {
        __half h = __float2half_rn(f[j]);
        a_hi[(size_t)i * 4 + j] = h;
        a_lo[(size_t)i * 4 + j] = __float2half_rn(f[j] - __half2float(h));
    }
}

// ---------------------------------------------------------------------------
// Transpose+split a weight:  w[K=4096, N] fp32  ->  wT[N, 4096] fp16 hi/lo
// ---------------------------------------------------------------------------
__global__ void transpose_w(const float* __restrict__ w,
                            __half* __restrict__ oh,
                            __half* __restrict__ ol, int N)
{
    __shared__ float t[32][33];
    const int tx = threadIdx.x, ty = threadIdx.y;
    const int n0 = blockIdx.x * 32, k0 = blockIdx.y * 32;
#pragma unroll
    for (int i = 0; i < 4; i++)
        t[ty + 8 * i][tx] = w[(size_t)(k0 + ty + 8 * i) * N + n0 + tx];
    __syncthreads();
#pragma unroll
    for (int i = 0; i < 4; i++) {
        float v = t[tx][ty + 8 * i];
        __half h = __float2half_rn(v);
        size_t off = (size_t)(n0 + ty + 8 * i) * DMODEL + k0 + tx;
        oh[off] = h;
        ol[off] = __float2half_rn(v - __half2float(h));
    }
}

// ---------------------------------------------------------------------------
// fp16-split HMMA GEMM, 4-stage cp.async pipeline.
//   C = A @ B; main pass Ah*Bh in f32 acc; corrections Ah*Bl + Al*Bh in a
//   separate f16 accumulator (merged at epilogue; correction sums ~1e-2 abs,
//   fp16 acc rounding ~1e-5 rel — negligible).
//   mode 0: plain fp32 C store (O projection).
//   mode 1: Q epilogue — RoPE + 1/sqrt(HD) scale + fp16 hi/lo split.
//   mode 2: fused K|V — cols [0,1024) = K (RoPE + split), [1024,2048) = V (fp16).
// ---------------------------------------------------------------------------
#define OP_BYTES    (128 * 80)
#define STAGE_BYTES (4 * OP_BYTES)          // 40960
#define NSTAGE      4
#define GH_SMEM     (NSTAGE * STAGE_BYTES)  // 163840

__global__ __launch_bounds__(256)
void gemm_hmma(const __half* __restrict__ Ah, const __half* __restrict__ Al,
               const __half* __restrict__ BhT, const __half* __restrict__ BlT,
               const __half* __restrict__ B2hT, const __half* __restrict__ B2lT,
               float* __restrict__ C, int N, int mode,
               const float* __restrict__ cosb, const float* __restrict__ sinb)
{
    extern __shared__ char smem_raw[];
    const uint32_t sb = smem_u32(smem_raw);
    const int tid  = threadIdx.x;
    const int wid  = tid >> 5;
    const int lane = tid & 31;
    const int wr   = wid & 3;
    const int wc   = wid >> 2;
    const int m0 = blockIdx.y * 128, n0 = blockIdx.x * 128;

    const __half* gAh = Ah + (size_t)m0 * DMODEL;
    const __half* gAl = Al + (size_t)m0 * DMODEL;
    const __half* gBh;
    const __half* gBl;
    if (mode == 2 && n0 >= KVD) {          // V half of the fused K|V launch
        gBh = B2hT + (size_t)(n0 - KVD) * DMODEL;
        gBl = B2lT + (size_t)(n0 - KVD) * DMODEL;
    } else {
        gBh = BhT + (size_t)n0 * DMODEL;
        gBl = BlT + (size_t)n0 * DMODEL;
    }

    auto stage = [&](int c, int s) {
        const uint32_t base = sb + s * STAGE_BYTES;
        const int koff = c * 32;
#pragma unroll
        for (int t = 0; t < 2; t++) {
            int seg = tid + t * 256;
            int row = seg >> 2, c16 = seg & 3;
            uint32_t so = row * 80 + c16 * 16;
            size_t   go = (size_t)row * DMODEL + koff + c16 * 8;
            cp16(base + so,                gAh + go);
            cp16(base + OP_BYTES + so,     gAl + go);
            cp16(base + 2 * OP_BYTES + so, gBh + go);
            cp16(base + 3 * OP_BYTES + so, gBl + go);
        }
        asm volatile("cp.async.commit_group;");
    };

    float acc[2][8][4];
    uint32_t ca[2][8][2];                 // f16 correction accumulators
#pragma unroll
    for (int i = 0; i < 2; i++)
#pragma unroll
        for (int j = 0; j < 8; j++) {
#pragma unroll
            for (int q = 0; q < 4; q++) acc[i][j][q] = 0.f;
            ca[i][j][0] = 0u; ca[i][j][1] = 0u;
        }

    const int mb = wr * 32;
    const uint32_t a_off = (mb + (lane & 15)) * 80 + ((lane >> 4) << 3) * 2;
    const uint32_t b_off = ((wc * 64) + (lane & 7) + ((lane >> 4) << 3)) * 80
                         + (((lane >> 3) & 1) << 3) * 2;

    stage(0, 0);
    stage(1, 1);
    stage(2, 2);
    const int NCH = DMODEL / 32;          // 128
    for (int c = 0; c < NCH; c++) {
        asm volatile("cp.async.wait_group 2;");
        __syncthreads();
        if (c + 3 < NCH) stage(c + 3, (c + 3) & 3);

        const uint32_t tAh = sb + (c & 3) * STAGE_BYTES;
        const uint32_t tAl = tAh + OP_BYTES;
        const uint32_t tBh = tAh + 2 * OP_BYTES;
        const uint32_t tBl = tAh + 3 * OP_BYTES;

#pragma unroll
        for (int ks = 0; ks < 2; ks++) {
            const uint32_t kb = ks * 32;
            uint32_t aH[2][4], aL[2][4], bH[4][4], bL[4][4];
            // main pass operands (reused by both corrections)
            ldsm_x4(aH[0], tAh + a_off + kb);
            ldsm_x4(aH[1], tAh + a_off + kb + 16 * 80);
#pragma unroll
            for (int q = 0; q < 4; q++)
                ldsm_x4(bH[q], tBh + b_off + kb + q * 16 * 80);
            // main: Ah*Bh -> f32 acc
#pragma unroll
            for (int i = 0; i < 2; i++)
#pragma unroll
                for (int q = 0; q < 4; q++) {
                    mma16816h(acc[i][2 * q],     aH[i], &bH[q][0]);
                    mma16816h(acc[i][2 * q + 1], aH[i], &bH[q][2]);
                }
            // correction 1: Ah*Bl -> f16 acc
#pragma unroll
            for (int q = 0; q < 4; q++)
                ldsm_x4(bL[q], tBl + b_off + kb + q * 16 * 80);
#pragma unroll
            for (int i = 0; i < 2; i++)
#pragma unroll
                for (int q = 0; q < 4; q++) {
                    mma16816hh(ca[i][2 * q],     aH[i], &bL[q][0]);
                    mma16816hh(ca[i][2 * q + 1], aH[i], &bL[q][2]);
                }
            // correction 2: Al*Bh -> f16 acc
            ldsm_x4(aL[0], tAl + a_off + kb);
            ldsm_x4(aL[1], tAl + a_off + kb + 16 * 80);
#pragma unroll
            for (int i = 0; i < 2; i++)
#pragma unroll
                for (int q = 0; q < 4; q++) {
                    mma16816hh(ca[i][2 * q],     aL[i], &bH[q][0]);
                    mma16816hh(ca[i][2 * q + 1], aL[i], &bH[q][2]);
                }
        }
    }

    // ---- epilogue ----
    const int rb   = wr * 32 + (lane >> 2);
    const int cb_l = wc * 64 + 2 * (lane & 3);
#pragma unroll
    for (int i = 0; i < 2; i++) {
        const int r0 = m0 + rb + i * 16;
        const int r1 = r0 + 8;
#pragma unroll
        for (int j = 0; j < 8; j++) {
            const int cc = n0 + cb_l + j * 8;     // even global column
            __half2 x0 = *(__half2*)&ca[i][j][0];
            __half2 x1 = *(__half2*)&ca[i][j][1];
            float v0 = acc[i][j][0] + __low2float(x0);
            float v1 = acc[i][j][1] + __high2float(x0);
            float v2 = acc[i][j][2] + __low2float(x1);
            float v3 = acc[i][j][3] + __high2float(x1);

            if (mode == 0) {
                *(float2*)&C[(size_t)r0 * N + cc] = make_float2(v0, v1);
                *(float2*)&C[(size_t)r1 * N + cc] = make_float2(v2, v3);
            } else if (mode == 1) {
                const int fi = (cc & 127) >> 1;
                float c0 = cosb[r0 * 64 + fi], s0 = sinb[r0 * 64 + fi];
                float c1 = cosb[r1 * 64 + fi], s1 = sinb[r1 * 64 + fi];
                float e0 = (v0 * c0 - v1 * s0) * ATT_SCALE;
                float o0 = (v1 * c0 + v0 * s0) * ATT_SCALE;
                float e1 = (v2 * c1 - v3 * s1) * ATT_SCALE;
                float o1 = (v3 * c1 + v2 * s1) * ATT_SCALE;
                __half eh0 = __float2half_rn(e0), oh0 = __float2half_rn(o0);
                __half eh1 = __float2half_rn(e1), oh1 = __float2half_rn(o1);
                *(__half2*)&g_qh[(size_t)r0 * DMODEL + cc] = __halves2half2(eh0, oh0);
                *(__half2*)&g_qh[(size_t)r1 * DMODEL + cc] = __halves2half2(eh1, oh1);
                *(__half2*)&g_ql[(size_t)r0 * DMODEL + cc] = __halves2half2(
                    __float2half_rn(e0 - __half2float(eh0)),
                    __float2half_rn(o0 - __half2float(oh0)));
                *(__half2*)&g_ql[(size_t)r1 * DMODEL + cc] = __halves2half2(
                    __float2half_rn(e1 - __half2float(eh1)),
                    __float2half_rn(o1 - __half2float(oh1)));
            } else {            // mode 2: K | V
                if (cc < KVD) { // K: rope, split
                    const int fi = (cc & 127) >> 1;
                    float c0 = cosb[r0 * 64 + fi], s0 = sinb[r0 * 64 + fi];
                    float c1 = cosb[r1 * 64 + fi], s1 = sinb[r1 * 64 + fi];
                    float e0 = v0 * c0 - v1 * s0, o0 = v1 * c0 + v0 * s0;
                    float e1 = v2 * c1 - v3 * s1, o1 = v3 * c1 + v2 * s1;
                    __half eh0 = __float2half_rn(e0), oh0 = __float2half_rn(o0);
                    __half eh1 = __float2half_rn(e1), oh1 = __float2half_rn(o1);
                    *(__half2*)&g_kh[(size_t)r0 * KVD + cc] = __halves2half2(eh0, oh0);
                    *(__half2*)&g_kh[(size_t)r1 * KVD + cc] = __halves2half2(eh1, oh1);
                    *(__half2*)&g_kl[(size_t)r0 * KVD + cc] = __halves2half2(
                        __float2half_rn(e0 - __half2float(eh0)),
                        __float2half_rn(o0 - __half2float(oh0)));
                    *(__half2*)&g_kl[(size_t)r1 * KVD + cc] = __halves2half2(
                        __float2half_rn(e1 - __half2float(eh1)),
                        __float2half_rn(o1 - __half2float(oh1)));
                } else {        // V: plain fp16
                    const int cv = cc - KVD;
                    *(__half2*)&g_vh[(size_t)r0 * KVD + cv] =
                        __halves2half2(__float2half_rn(v0), __float2half_rn(v1));
                    *(__half2*)&g_vh[(size_t)r1 * KVD + cv] =
                        __halves2half2(__float2half_rn(v2), __float2half_rn(v3));
                }
            }
        }
    }
}

// ---------------------------------------------------------------------------
// HMMA flash attention, FA2-style register softmax (unchanged from R15).
// ---------------------------------------------------------------------------
#define BQ 128
#define BK 64
#define KSTR 272
#define AOFF_QH 0
#define AOFF_QL (BQ * KSTR)
#define AOFF_ST (2 * BQ * KSTR)
#define KV_STG  (3 * BK * KSTR)
#define FA_SMEM (AOFF_ST + 2 * KV_STG)

__global__ __launch_bounds__(256)
void attn_flash()
{
    extern __shared__ char smem_raw[];
    const uint32_t sb = smem_u32(smem_raw);
    const int tid = threadIdx.x, lane = tid & 31, w = tid >> 5;
    const int qt = (int)gridDim.x - 1 - (int)blockIdx.x;
    const int h = blockIdx.y, kvh = h & (NKVH - 1);
    const int q0 = qt * BQ;
    const int nkt = 2 * qt + 2;
    const int rowbase = w * 16;

    const uint32_t aoffQ = (rowbase + (lane & 15)) * KSTR + ((lane >> 4) << 4);
    const uint32_t boffK = ((lane & 7) + ((lane >> 4) << 3)) * KSTR + (((lane >> 3) & 1) << 4);
    const uint32_t boffV = ((lane & 7) + (((lane >> 3) & 1) << 3)) * KSTR + ((lane >> 4) << 4);

#pragma unroll
    for (int t = 0; t < 8; t++) {
        int seg = tid + t * 256;
        int row = seg >> 4, sg = seg & 15;
        size_t g = (size_t)(q0 + row) * DMODEL + h * HDIM + sg * 8;
        cp16(sb + AOFF_QH + row * KSTR + sg * 16, g_qh + g);
        cp16(sb + AOFF_QL + row * KSTR + sg * 16, g_ql + g);
    }
    asm volatile("cp.async.commit_group;");

    auto stage_kv = [&](int kt, int s) {
        const uint32_t base = sb + AOFF_ST + s * KV_STG;
        const int k0 = kt * BK;
#pragma unroll
        for (int t = 0; t < 4; t++) {
            int seg = tid + t * 256;
            int row = seg >> 4, sg = seg & 15;
            size_t g = (size_t)(k0 + row) * KVD + kvh * HDIM + sg * 8;
            cp16(base + row * KSTR + sg * 16,                 g_kh + g);
            cp16(base + BK * KSTR + row * KSTR + sg * 16,     g_kl + g);
            cp16(base + 2 * BK * KSTR + row * KSTR + sg * 16, g_vh + g);
        }
        asm volatile("cp.async.commit_group;");
    };

    stage_kv(0, 0);

    float oacc[16][4];
#pragma unroll
    for (int nt = 0; nt < 16; nt++)
#pragma unroll
        for (int q = 0; q < 4; q++) oacc[nt][q] = 0.f;

    float m0 = -INFINITY, m1 = -INFINITY, l0 = 0.f, l1 = 0.f;
    const int gq0 = q0 + rowbase + (lane >> 2);
    const int gq1 = gq0 + 8;

    for (int kt = 0; kt < nkt; kt++) {
        const int k0 = kt * BK;
        const int s = kt & 1;
        asm volatile("cp.async.wait_group 0;");
        __syncthreads();
        if (kt + 1 < nkt) stage_kv(kt + 1, s ^ 1);

        const bool active = (k0 <= q0 + rowbase + 15);
        if (active) {
            const uint32_t kvb = sb + AOFF_ST + s * KV_STG;

            float sacc[8][4];
#pragma unroll
            for (int nt = 0; nt < 8; nt++)
#pragma unroll
                for (int q = 0; q < 4; q++) sacc[nt][q] = 0.f;

#pragma unroll
            for (int pass = 0; pass < 3; pass++) {
                const uint32_t qb = sb + (pass == 1 ? AOFF_QL : AOFF_QH) + aoffQ;
                const uint32_t kb = kvb + (pass == 2 ? BK * KSTR : 0) + boffK;
#pragma unroll
                for (int ks = 0; ks < 8; ks++) {
                    uint32_t a[4];
                    ldsm_x4(a, qb + ks * 32);
#pragma unroll
                    for (int g2 = 0; g2 < 4; g2++) {
                        uint32_t b[4];
                        ldsm_x4(b, kb + g2 * 16 * KSTR + ks * 32);
                        mma16816h(sacc[2 * g2],     a, &b[0]);
                        mma16816h(sacc[2 * g2 + 1], a, &b[2]);
                    }
                }
            }

            const int colb = k0 + 2 * (lane & 3);
            float mx0 = -1e30f, mx1 = -1e30f;
#pragma unroll
            for (int nt = 0; nt < 8; nt++) {
                int c0 = colb + 8 * nt, c1 = c0 + 1;
                if (c0 > gq0) sacc[nt][0] = -1e30f;
                if (c1 > gq0) sacc[nt][1] = -1e30f;
                if (c0 > gq1) sacc[nt][2] = -1e30f;
                if (c1 > gq1) sacc[nt][3] = -1e30f;
                mx0 = fmaxf(mx0, fmaxf(sacc[nt][0], sacc[nt][1]));
                mx1 = fmaxf(mx1, fmaxf(sacc[nt][2], sacc[nt][3]));
            }
            mx0 = fmaxf(mx0, __shfl_xor_sync(0xffffffffu, mx0, 1));
            mx0 = fmaxf(mx0, __shfl_xor_sync(0xffffffffu, mx0, 2));
            mx1 = fmaxf(mx1, __shfl_xor_sync(0xffffffffu, mx1, 1));
            mx1 = fmaxf(mx1, __shfl_xor_sync(0xffffffffu, mx1, 2));
            float mn0 = fmaxf(m0, mx0), mn1 = fmaxf(m1, mx1);
            float al0 = __expf(m0 - mn0), al1 = __expf(m1 - mn1);
            m0 = mn0; m1 = mn1;

            uint32_t ph[4][4], pl[4][4];
            float ls0 = 0.f, ls1 = 0.f;
#pragma unroll
            for (int nt = 0; nt < 8; nt++) {
                float p0 = __expf(sacc[nt][0] - mn0);
                float p1 = __expf(sacc[nt][1] - mn0);
                float p2 = __expf(sacc[nt][2] - mn1);
                float p3 = __expf(sacc[nt][3] - mn1);
                ls0 += p0 + p1; ls1 += p2 + p3;
                __half h0 = __float2half_rn(p0), h1 = __float2half_rn(p1);
                __half h2 = __float2half_rn(p2), h3 = __float2half_rn(p3);
                int ks = nt >> 1, half = (nt & 1) << 1;
                ph[ks][half]     = packh2(h0, h1);
                ph[ks][half + 1] = packh2(h2, h3);
                pl[ks][half]     = packh2(__float2half_rn(p0 - __half2float(h0)),
                                          __float2half_rn(p1 - __half2float(h1)));
                pl[ks][half + 1] = packh2(__float2half_rn(p2 - __half2float(h2)),
                                          __float2half_rn(p3 - __half2float(h3)));
            }
            ls0 += __shfl_xor_sync(0xffffffffu, ls0, 1);
            ls0 += __shfl_xor_sync(0xffffffffu, ls0, 2);
            ls1 += __shfl_xor_sync(0xffffffffu, ls1, 1);
            ls1 += __shfl_xor_sync(0xffffffffu, ls1, 2);
            l0 = l0 * al0 + ls0;
            l1 = l1 * al1 + ls1;

#pragma unroll
            for (int nt = 0; nt < 16; nt++) {
                oacc[nt][0] *= al0; oacc[nt][1] *= al0;
                oacc[nt][2] *= al1; oacc[nt][3] *= al1;
            }

            const uint32_t vb = kvb + 2 * BK * KSTR + boffV;
#pragma unroll
            for (int ks = 0; ks < 4; ks++) {
                uint32_t vfr[8][4];
#pragma unroll
                for (int g2 = 0; g2 < 8; g2++)
                    ldsm_x4_t(vfr[g2], vb + ks * 16 * KSTR + g2 * 32);
#pragma unroll
                for (int g2 = 0; g2 < 8; g2++) {
                    mma16816h(oacc[2 * g2],     ph[ks], &vfr[g2][0]);
                    mma16816h(oacc[2 * g2 + 1], ph[ks], &vfr[g2][2]);
                }
#pragma unroll
                for (int g2 = 0; g2 < 8; g2++) {
                    mma16816h(oacc[2 * g2],     pl[ks], &vfr[g2][0]);
                    mma16816h(oacc[2 * g2 + 1], pl[ks], &vfr[g2][2]);
                }
            }
        }
        __syncthreads();
    }

    // epilogue: normalize, fp16 hi/lo split (feeds fp16 O-projection)
    {
        const float inv0 = 1.f / l0;
        const float inv1 = 1.f / l1;
#pragma unroll
        for (int nt = 0; nt < 16; nt++) {
            int c = nt * 8 + 2 * (lane & 3);
            size_t i0 = (size_t)gq0 * DMODEL + h * HDIM + c;
            size_t i1 = (size_t)gq1 * DMODEL + h * HDIM + c;
            float v0 = oacc[nt][0] * inv0, v1 = oacc[nt][1] * inv0;
            float v2 = oacc[nt][2] * inv1, v3 = oacc[nt][3] * inv1;
            __half h0 = __float2half_rn(v0), h1 = __float2half_rn(v1);
            __half h2 = __float2half_rn(v2), h3 = __float2half_rn(v3);
            *(__half2*)&att_hi[i0] = __halves2half2(h0, h1);
            *(__half2*)&att_hi[i1] = __halves2half2(h2, h3);
            *(__half2*)&att_lo[i0] = __halves2half2(
                __float2half_rn(v0 - __half2float(h0)),
                __float2half_rn(v1 - __half2float(h1)));
            *(__half2*)&att_lo[i1] = __halves2half2(
                __float2half_rn(v2 - __half2float(h2)),
                __float2half_rn(v3 - __half2float(h3)));
        }
    }
}

// ---------------------------------------------------------------------------
// Launch
// ---------------------------------------------------------------------------
extern "C" void kernel_launch(void* const* d_in, const int* in_sizes, int n_in,
                              void* d_out, int out_size)
{
    const float* x    = (const float*)d_in[0];
    const float* wq   = (const float*)d_in[1];
    const float* wk   = (const float*)d_in[2];
    const float* wv   = (const float*)d_in[3];
    const float* wo   = (const float*)d_in[4];
    const float* fcos = (const float*)d_in[5];
    const float* fsin = (const float*)d_in[6];
    float* out = (float*)d_out;

    __half *pah, *pal, *path, *patl;
    __half *pwqh, *pwql, *pwkh, *pwkl, *pwvh, *pwvl, *pwoh, *pwol;
    cudaGetSymbolAddress((void**)&pah, a_hi);
    cudaGetSymbolAddress((void**)&pal, a_lo);
    cudaGetSymbolAddress((void**)&path, att_hi);
    cudaGetSymbolAddress((void**)&patl, att_lo);
    cudaGetSymbolAddress((void**)&pwqh, wqT_h);
    cudaGetSymbolAddress((void**)&pwql, wqT_l);
    cudaGetSymbolAddress((void**)&pwkh, wkT_h);
    cudaGetSymbolAddress((void**)&pwkl, wkT_l);
    cudaGetSymbolAddress((void**)&pwvh, wvT_h);
    cudaGetSymbolAddress((void**)&pwvl, wvT_l);
    cudaGetSymbolAddress((void**)&pwoh, woT_h);
    cudaGetSymbolAddress((void**)&pwol, woT_l);

    cudaFuncSetAttribute(gemm_hmma, cudaFuncAttributeMaxDynamicSharedMemorySize, GH_SMEM);
    cudaFuncSetAttribute(attn_flash, cudaFuncAttributeMaxDynamicSharedMemorySize, FA_SMEM);

    // Split x; transpose+split weights (fp16 hi/lo)
    convert_x<<<(SEQ * DMODEL / 4) / 256, 256>>>(x);
    transpose_w<<<dim3(DMODEL / 32, DMODEL / 32), dim3(32, 8)>>>(wq, pwqh, pwql, DMODEL);
    transpose_w<<<dim3(KVD / 32, DMODEL / 32), dim3(32, 8)>>>(wk, pwkh, pwkl, KVD);
    transpose_w<<<dim3(KVD / 32, DMODEL / 32), dim3(32, 8)>>>(wv, pwvh, pwvl, KVD);
    transpose_w<<<dim3(DMODEL / 32, DMODEL / 32), dim3(32, 8)>>>(wo, pwoh, pwol, DMODEL);

    // Q projection (mode 1: fused RoPE+scale+split)
    gemm_hmma<<<dim3(DMODEL / 128, SEQ / 128), 256, GH_SMEM>>>(
        pah, pal, pwqh, pwql, pwqh, pwql, out, DMODEL, 1, fcos, fsin);

    // Fused K|V projection (mode 2): one single-wave launch
    gemm_hmma<<<dim3((2 * KVD) / 128, SEQ / 128), 256, GH_SMEM>>>(
        pah, pal, pwkh, pwkl, pwvh, pwvl, out, 2 * KVD, 2, fcos, fsin);

    // Flash attention (HMMA, register softmax)
    attn_flash<<<dim3(SEQ / BQ, NHEAD), 256, FA_SMEM>>>();

    // Output projection (mode 0) -> d_out
    gemm_hmma<<<dim3(DMODEL / 128, SEQ / 128), 256, GH_SMEM>>>(
        path, patl, pwoh, pwol, pwoh, pwol, out, DMODEL, 0, fcos, fsin);
}